// round 14
// baseline (speedup 1.0000x reference)
#include <cuda_runtime.h>
#include <cuda_bf16.h>
#include <cstdint>

#define MAX_B  32768
#define H      64
#define TPB    256          // 8 warps = 8 batch groups per block

__device__ int g_soff[MAX_B];       // full exclusive offsets
__device__ int g_toff[MAX_B];
__device__ int g_ready = 0;         // producer flag (reset each replay)
__device__ int g_done  = 0;         // completion counter for reset

// ---------------------------------------------------------------------------
// helpers
// ---------------------------------------------------------------------------
__device__ __forceinline__ float4 f4add(float4 a, float4 b) {
    return make_float4(a.x + b.x, a.y + b.y, a.z + b.z, a.w + b.w);
}
__device__ __forceinline__ int pick_idx(int ia, int ib, int r) {
    const int v = __shfl_sync(0xffffffffu, ia, r & 31);
    const int w = __shfl_sync(0xffffffffu, ib, r & 31);
    return (r < 32) ? v : w;
}
template <int N>
__device__ __forceinline__ void red16(float (&v)[N]) {
    #pragma unroll
    for (int o = 8; o > 0; o >>= 1) {
        #pragma unroll
        for (int k = 0; k < N; k++)
            v[k] += __shfl_xor_sync(0xffffffffu, v[k], o);
    }
}

// ---------------------------------------------------------------------------
// Block-0 producer: full exclusive scan of size/tsize into g_soff/g_toff.
// Two passes (sum, then prefix+store); second pass re-reads L1/L2-hot data.
// 256 threads, chunk = ceil(B/256) rounded to 4.
// ---------------------------------------------------------------------------
__device__ void block0_scan(const int* __restrict__ size,
                            const int* __restrict__ tsize, int B) {
    __shared__ int sw[8], tw[8];
    const int t = threadIdx.x, lane = t & 31, wid = t >> 5;
    const int chunk = (((B + TPB - 1) / TPB) + 3) & ~3;
    const int e0 = t * chunk;

    // pass 1: per-thread sums
    int s0 = 0, t0 = 0;
    for (int j = 0; j < chunk; j += 4) {
        const int i = e0 + j;
        if (i + 3 < B) {
            const int4 a = *(const int4*)(size  + i);
            const int4 c = *(const int4*)(tsize + i);
            s0 += a.x + a.y + a.z + a.w;
            t0 += c.x + c.y + c.z + c.w;
        } else {
            for (int k = i; k < B && k < i + 4; k++) { s0 += size[k]; t0 += tsize[k]; }
        }
    }
    // block scan of 256 partials
    int si = s0, ti = t0;
    #pragma unroll
    for (int o = 1; o < 32; o <<= 1) {
        const int a = __shfl_up_sync(0xffffffffu, si, o);
        const int c = __shfl_up_sync(0xffffffffu, ti, o);
        if (lane >= o) { si += a; ti += c; }
    }
    if (lane == 31) { sw[wid] = si; tw[wid] = ti; }
    __syncthreads();
    if (wid == 0 && lane < 8) {
        int a = sw[lane], c = tw[lane];
        #pragma unroll
        for (int o = 1; o < 8; o <<= 1) {
            const int x = __shfl_up_sync(0xffu, a, o);
            const int y = __shfl_up_sync(0xffu, c, o);
            if (lane >= o) { a += x; c += y; }
        }
        sw[lane] = a; tw[lane] = c;
    }
    __syncthreads();

    // pass 2: write exclusive offsets
    int ps = (wid ? sw[wid - 1] : 0) + si - s0;
    int pt = (wid ? tw[wid - 1] : 0) + ti - t0;
    for (int j = 0; j < chunk; j += 4) {
        const int i = e0 + j;
        if (i + 3 < B) {
            const int4 a = *(const int4*)(size  + i);
            const int4 c = *(const int4*)(tsize + i);
            int4 os, ot;
            os.x = ps;          ot.x = pt;
            os.y = ps + a.x;    ot.y = pt + c.x;
            os.z = os.y + a.y;  ot.z = ot.y + c.y;
            os.w = os.z + a.z;  ot.w = ot.z + c.z;
            *(int4*)(g_soff + i) = os;
            *(int4*)(g_toff + i) = ot;
            ps = os.w + a.w;    pt = ot.w + c.w;
        } else {
            for (int k = i; k < B && k < i + 4; k++) {
                g_soff[k] = ps; g_toff[k] = pt;
                ps += size[k];  pt += tsize[k];
            }
        }
    }
}

// ---------------------------------------------------------------------------
// Fused kernel: block 0 produces offsets, sets g_ready; all other blocks
// spin-wait (leader poll + acquire), then everyone runs the R4 champion body.
// A grid-wide done-counter resets g_ready/g_done for the next graph replay.
// ---------------------------------------------------------------------------
__global__ void __launch_bounds__(TPB)
simplex_kernel(const int*   __restrict__ user,
               const int*   __restrict__ item,
               const int*   __restrict__ tgt,
               const int*   __restrict__ size,
               const int*   __restrict__ tsize,
               const float* __restrict__ uw,
               const float* __restrict__ iw,
               float*       __restrict__ out,
               int B) {
    // ---- produce / wait for offsets ----
    if (blockIdx.x == 0) {
        block0_scan(size, tsize, B);
        __syncthreads();
        if (threadIdx.x == 0) {
            __threadfence();                       // release offsets
            *(volatile int*)&g_ready = 1;
        }
        __syncthreads();
    } else {
        if (threadIdx.x == 0) {
            while (*(volatile int*)&g_ready == 0) __nanosleep(64);
            __threadfence();                       // acquire offsets
        }
        __syncthreads();
    }

    const int b = blockIdx.x * (TPB >> 5) + (threadIdx.x >> 5);
    if (b < B) {
        const int lane = threadIdx.x & 31;
        const int q    = lane & 15;
        const int h    = lane >> 4;

        const int soff = g_soff[b];
        const int toff = g_toff[b];
        const int sz   = size[b];
        const int tsz  = tsize[b];

        // ---- item segment sum: chunks of 64 indices, 8 rows / 4 loads per iter
        float4 acc0 = make_float4(0.f,0.f,0.f,0.f);
        float4 acc1 = make_float4(0.f,0.f,0.f,0.f);
        for (int cb = 0; cb < sz; cb += 64) {
            const int n  = min(sz - cb, 64);
            const int ia = (lane      < n) ? __ldg(&item[soff + cb + lane])      : 0;
            const int ib = (lane + 32 < n) ? __ldg(&item[soff + cb + 32 + lane]) : 0;

            int base = 0;
            for (; base + 8 <= n; base += 8) {
                const int i0 = pick_idx(ia, ib, base + 0 + h);
                const int i1 = pick_idx(ia, ib, base + 2 + h);
                const int i2 = pick_idx(ia, ib, base + 4 + h);
                const int i3 = pick_idx(ia, ib, base + 6 + h);
                const float4 v0 = __ldg((const float4*)&iw[(size_t)i0 * H + 4 * q]);
                const float4 v1 = __ldg((const float4*)&iw[(size_t)i1 * H + 4 * q]);
                const float4 v2 = __ldg((const float4*)&iw[(size_t)i2 * H + 4 * q]);
                const float4 v3 = __ldg((const float4*)&iw[(size_t)i3 * H + 4 * q]);
                acc0 = f4add(acc0, f4add(v0, v2));
                acc1 = f4add(acc1, f4add(v1, v3));
            }
            for (; base < n; base += 2) {
                const int r = base + h;
                if (r < n) {
                    const int ii = pick_idx(ia, ib, r);
                    acc0 = f4add(acc0, __ldg((const float4*)&iw[(size_t)ii * H + 4 * q]));
                }
            }
        }
        float4 acc = f4add(acc0, acc1);
        acc.x += __shfl_xor_sync(0xffffffffu, acc.x, 16);
        acc.y += __shfl_xor_sync(0xffffffffu, acc.y, 16);
        acc.z += __shfl_xor_sync(0xffffffffu, acc.z, 16);
        acc.w += __shfl_xor_sync(0xffffffffu, acc.w, 16);

        // ---- emb = 0.5*user + 0.5*mean ----
        const int ui   = max(soff + sz - 1, 0);
        const int urow = __ldg(&user[ui]);
        const float4 ue = __ldg((const float4*)&uw[(size_t)urow * H + 4 * q]);
        const float inv = 0.5f / ((float)sz + 1e-6f);
        float4 emb;
        emb.x = 0.5f * ue.x + acc.x * inv;
        emb.y = 0.5f * ue.y + acc.y * inv;
        emb.z = 0.5f * ue.z + acc.z * inv;
        emb.w = 0.5f * ue.w + acc.w * inv;

        // ---- center + L2 normalize (width-16, replicated in both halves) ----
        float v2r[2];
        v2r[0] = emb.x + emb.y + emb.z + emb.w;
        v2r[1] = emb.x*emb.x + emb.y*emb.y + emb.z*emb.z + emb.w*emb.w;
        red16<2>(v2r);
        const float mean = v2r[0] * (1.0f / H);
        const float ss   = fmaxf(v2r[1] - v2r[0] * mean, 0.0f);
        const float invn = 1.0f / fmaxf(sqrtf(ss), 1e-12f);
        float4 en;
        en.x = (emb.x - mean) * invn;
        en.y = (emb.y - mean) * invn;
        en.z = (emb.z - mean) * invn;
        en.w = (emb.w - mean) * invn;

        // ---- targets: two per iteration (one per half). sum(en)==0 so
        //      dot(center(te), en) == dot(te, en). ----
        for (int cb = 0; cb < tsz; cb += 32) {
            const int n  = min(tsz - cb, 32);
            const int ta = (lane < n) ? __ldg(&tgt[toff + cb + lane]) : 0;
            for (int base = 0; base < n; base += 2) {
                const int t = base + h;
                if (t < n) {
                    const int row = __shfl_sync(0xffffffffu, ta, t);
                    const float4 te = __ldg((const float4*)&iw[(size_t)row * H + 4 * q]);
                    float v3[3];
                    v3[0] = te.x + te.y + te.z + te.w;
                    v3[1] = te.x*te.x + te.y*te.y + te.z*te.z + te.w*te.w;
                    v3[2] = te.x*en.x + te.y*en.y + te.z*en.z + te.w*en.w;
                    red16<3>(v3);
                    if (q == 0) {
                        const float mt  = v3[0] * (1.0f / H);
                        const float sst = fmaxf(v3[1] - v3[0] * mt, 0.0f);
                        out[toff + cb + t] = v3[2] / fmaxf(sqrtf(sst), 1e-12f);
                    }
                }
            }
        }
    }

    // ---- replay-safe reset: last block to finish clears the flag ----
    __syncthreads();
    if (threadIdx.x == 0) {
        __threadfence();
        const int d = atomicAdd(&g_done, 1);
        if (d == (int)gridDim.x - 1) {
            g_ready = 0;
            __threadfence();
            g_done = 0;
            __threadfence();
        }
    }
}

// ---------------------------------------------------------------------------
extern "C" void kernel_launch(void* const* d_in, const int* in_sizes, int n_in,
                              void* d_out, int out_size) {
    const int*   user        = (const int*)d_in[0];
    const int*   item        = (const int*)d_in[1];
    const int*   target_item = (const int*)d_in[2];
    const int*   size        = (const int*)d_in[3];
    const int*   target_size = (const int*)d_in[4];
    const float* user_weight = (const float*)d_in[5];
    const float* item_weight = (const float*)d_in[6];
    float*       out         = (float*)d_out;

    const int B    = in_sizes[3];
    const int wpb  = TPB >> 5;
    const int grid = (B + wpb - 1) / wpb;

    simplex_kernel<<<grid, TPB>>>(user, item, target_item, size, target_size,
                                  user_weight, item_weight, out, B);
}

// round 15
// speedup vs baseline: 1.2556x; 1.2556x over previous
#include <cuda_runtime.h>
#include <cuda_bf16.h>
#include <cstdint>

#define MAX_B  32768
#define H      64
#define TPB    256          // 8 warps = 8 batch groups per block
#define SCB    512          // elements per scan block

__device__ int g_soff[MAX_B];   // exclusive prefix of size
__device__ int g_toff[MAX_B];   // exclusive prefix of target_size

// ---------------------------------------------------------------------------
// Kernel 1: parallel redundant-prefix scan. Block g computes
// base = sum(size[0 : 512g]) by direct (parallel, L2-hot) re-read, then
// block-scans its own 512 elements and writes exact exclusive offsets.
// No inter-block communication; all blocks run concurrently.
// ---------------------------------------------------------------------------
__global__ void __launch_bounds__(SCB)
scan_par_kernel(const int* __restrict__ size, const int* __restrict__ tsize,
                int B) {
    __shared__ int rs[16], rt[16];
    __shared__ int base_s, base_t;
    const int g = blockIdx.x, t = threadIdx.x, lane = t & 31, wid = t >> 5;
    const int start = g * SCB;

    // ---- base = sum of all prior elements (parallel strided read) ----
    int ps = 0, pt = 0;
    for (int i = t; i < start && i < B; i += SCB) {
        ps += size[i]; pt += tsize[i];
    }
    #pragma unroll
    for (int o = 16; o > 0; o >>= 1) {
        ps += __shfl_xor_sync(0xffffffffu, ps, o);
        pt += __shfl_xor_sync(0xffffffffu, pt, o);
    }
    if (lane == 0) { rs[wid] = ps; rt[wid] = pt; }
    __syncthreads();
    if (t == 0) {
        int a = 0, c = 0;
        #pragma unroll
        for (int k = 0; k < 16; k++) { a += rs[k]; c += rt[k]; }
        base_s = a; base_t = c;
    }
    __syncthreads();

    // ---- block exclusive scan of this block's 512 elements ----
    const int i  = start + t;
    const int sv = (i < B) ? size[i]  : 0;
    const int tv = (i < B) ? tsize[i] : 0;
    int si = sv, ti = tv;
    #pragma unroll
    for (int o = 1; o < 32; o <<= 1) {
        const int a = __shfl_up_sync(0xffffffffu, si, o);
        const int c = __shfl_up_sync(0xffffffffu, ti, o);
        if (lane >= o) { si += a; ti += c; }
    }
    if (lane == 31) { rs[wid] = si; rt[wid] = ti; }
    __syncthreads();
    if (wid == 0 && lane < 16) {
        int a = rs[lane], c = rt[lane];
        #pragma unroll
        for (int o = 1; o < 16; o <<= 1) {
            const int x = __shfl_up_sync(0xffffu, a, o);
            const int y = __shfl_up_sync(0xffffu, c, o);
            if (lane >= o) { a += x; c += y; }
        }
        rs[lane] = a; rt[lane] = c;
    }
    __syncthreads();

    if (i < B) {
        const int es = (wid ? rs[wid - 1] : 0) + si - sv;
        const int et = (wid ? rt[wid - 1] : 0) + ti - tv;
        g_soff[i] = base_s + es;
        g_toff[i] = base_t + et;
    }
}

// ---------------------------------------------------------------------------
// helpers
// ---------------------------------------------------------------------------
__device__ __forceinline__ float4 f4add(float4 a, float4 b) {
    return make_float4(a.x + b.x, a.y + b.y, a.z + b.z, a.w + b.w);
}
__device__ __forceinline__ int pick_idx(int ia, int ib, int r) {
    const int v = __shfl_sync(0xffffffffu, ia, r & 31);
    const int w = __shfl_sync(0xffffffffu, ib, r & 31);
    return (r < 32) ? v : w;
}
template <int N>
__device__ __forceinline__ void red16(float (&v)[N]) {
    #pragma unroll
    for (int o = 8; o > 0; o >>= 1) {
        #pragma unroll
        for (int k = 0; k < N; k++)
            v[k] += __shfl_xor_sync(0xffffffffu, v[k], o);
    }
}

// ---------------------------------------------------------------------------
// Kernel 2 (exact round-4 champion body): one warp per batch group;
// 16 lanes/row (quad q), halves h=0/1; item loop = 8 rows / 4 independent
// LDG.128 per lane-pair iteration; serialized 2-per-iter target loop.
// ---------------------------------------------------------------------------
__global__ void __launch_bounds__(TPB)
simplex_kernel(const int*   __restrict__ user,
               const int*   __restrict__ item,
               const int*   __restrict__ tgt,
               const int*   __restrict__ size,
               const int*   __restrict__ tsize,
               const float* __restrict__ uw,
               const float* __restrict__ iw,
               float*       __restrict__ out,
               int B) {
    const int b = blockIdx.x * (TPB >> 5) + (threadIdx.x >> 5);
    if (b >= B) return;
    const int lane = threadIdx.x & 31;
    const int q    = lane & 15;
    const int h    = lane >> 4;

    const int soff = g_soff[b];
    const int toff = g_toff[b];
    const int sz   = size[b];
    const int tsz  = tsize[b];

    // ---- item segment sum: chunks of 64 indices, 8 rows / 4 loads per iter
    float4 acc0 = make_float4(0.f,0.f,0.f,0.f);
    float4 acc1 = make_float4(0.f,0.f,0.f,0.f);
    for (int cb = 0; cb < sz; cb += 64) {
        const int n  = min(sz - cb, 64);
        const int ia = (lane      < n) ? __ldg(&item[soff + cb + lane])      : 0;
        const int ib = (lane + 32 < n) ? __ldg(&item[soff + cb + 32 + lane]) : 0;

        int base = 0;
        for (; base + 8 <= n; base += 8) {
            const int i0 = pick_idx(ia, ib, base + 0 + h);
            const int i1 = pick_idx(ia, ib, base + 2 + h);
            const int i2 = pick_idx(ia, ib, base + 4 + h);
            const int i3 = pick_idx(ia, ib, base + 6 + h);
            const float4 v0 = __ldg((const float4*)&iw[(size_t)i0 * H + 4 * q]);
            const float4 v1 = __ldg((const float4*)&iw[(size_t)i1 * H + 4 * q]);
            const float4 v2 = __ldg((const float4*)&iw[(size_t)i2 * H + 4 * q]);
            const float4 v3 = __ldg((const float4*)&iw[(size_t)i3 * H + 4 * q]);
            acc0 = f4add(acc0, f4add(v0, v2));
            acc1 = f4add(acc1, f4add(v1, v3));
        }
        for (; base < n; base += 2) {
            const int r = base + h;
            if (r < n) {
                const int ii = pick_idx(ia, ib, r);
                acc0 = f4add(acc0, __ldg((const float4*)&iw[(size_t)ii * H + 4 * q]));
            }
        }
    }
    float4 acc = f4add(acc0, acc1);
    acc.x += __shfl_xor_sync(0xffffffffu, acc.x, 16);
    acc.y += __shfl_xor_sync(0xffffffffu, acc.y, 16);
    acc.z += __shfl_xor_sync(0xffffffffu, acc.z, 16);
    acc.w += __shfl_xor_sync(0xffffffffu, acc.w, 16);

    // ---- emb = 0.5*user + 0.5*mean ----
    const int ui   = max(soff + sz - 1, 0);
    const int urow = __ldg(&user[ui]);
    const float4 ue = __ldg((const float4*)&uw[(size_t)urow * H + 4 * q]);
    const float inv = 0.5f / ((float)sz + 1e-6f);
    float4 emb;
    emb.x = 0.5f * ue.x + acc.x * inv;
    emb.y = 0.5f * ue.y + acc.y * inv;
    emb.z = 0.5f * ue.z + acc.z * inv;
    emb.w = 0.5f * ue.w + acc.w * inv;

    // ---- center + L2 normalize (width-16, replicated in both halves) ----
    float v2r[2];
    v2r[0] = emb.x + emb.y + emb.z + emb.w;
    v2r[1] = emb.x*emb.x + emb.y*emb.y + emb.z*emb.z + emb.w*emb.w;
    red16<2>(v2r);
    const float mean = v2r[0] * (1.0f / H);
    const float ss   = fmaxf(v2r[1] - v2r[0] * mean, 0.0f);
    const float invn = 1.0f / fmaxf(sqrtf(ss), 1e-12f);
    float4 en;
    en.x = (emb.x - mean) * invn;
    en.y = (emb.y - mean) * invn;
    en.z = (emb.z - mean) * invn;
    en.w = (emb.w - mean) * invn;

    // ---- targets: two per iteration (one per half). sum(en)==0 so
    //      dot(center(te), en) == dot(te, en). ----
    for (int cb = 0; cb < tsz; cb += 32) {
        const int n  = min(tsz - cb, 32);
        const int ta = (lane < n) ? __ldg(&tgt[toff + cb + lane]) : 0;
        for (int base = 0; base < n; base += 2) {
            const int t = base + h;
            if (t < n) {
                const int row = __shfl_sync(0xffffffffu, ta, t);
                const float4 te = __ldg((const float4*)&iw[(size_t)row * H + 4 * q]);
                float v3[3];
                v3[0] = te.x + te.y + te.z + te.w;
                v3[1] = te.x*te.x + te.y*te.y + te.z*te.z + te.w*te.w;
                v3[2] = te.x*en.x + te.y*en.y + te.z*en.z + te.w*en.w;
                red16<3>(v3);
                if (q == 0) {
                    const float mt  = v3[0] * (1.0f / H);
                    const float sst = fmaxf(v3[1] - v3[0] * mt, 0.0f);
                    out[toff + cb + t] = v3[2] / fmaxf(sqrtf(sst), 1e-12f);
                }
            }
        }
    }
}

// ---------------------------------------------------------------------------
extern "C" void kernel_launch(void* const* d_in, const int* in_sizes, int n_in,
                              void* d_out, int out_size) {
    const int*   user        = (const int*)d_in[0];
    const int*   item        = (const int*)d_in[1];
    const int*   target_item = (const int*)d_in[2];
    const int*   size        = (const int*)d_in[3];
    const int*   target_size = (const int*)d_in[4];
    const float* user_weight = (const float*)d_in[5];
    const float* item_weight = (const float*)d_in[6];
    float*       out         = (float*)d_out;

    const int B     = in_sizes[3];
    const int nscan = (B + SCB - 1) / SCB;
    const int wpb   = TPB >> 5;
    const int grid  = (B + wpb - 1) / wpb;

    scan_par_kernel<<<nscan, SCB>>>(size, target_size, B);
    simplex_kernel<<<grid, TPB>>>(user, item, target_item, size, target_size,
                                  user_weight, item_weight, out, B);
}

// round 16
// speedup vs baseline: 1.3231x; 1.0538x over previous
#include <cuda_runtime.h>
#include <cuda_bf16.h>
#include <cstdint>

#define MAX_B  32768
#define H      64
#define TPB    256          // 8 warps = 8 batch groups per block
#define SCB    512          // elements per scan block

__device__ int g_soff[MAX_B];   // exclusive prefix of size
__device__ int g_toff[MAX_B];   // exclusive prefix of target_size

// ---------------------------------------------------------------------------
// Kernel 1: parallel redundant-prefix scan. Block g computes
// base = sum(size[0 : 512g]) by direct (parallel, L2-hot) re-read, then
// block-scans its own 512 elements and writes exact exclusive offsets.
// No inter-block communication; all blocks run concurrently.
// ---------------------------------------------------------------------------
__global__ void __launch_bounds__(SCB)
scan_par_kernel(const int* __restrict__ size, const int* __restrict__ tsize,
                int B) {
    __shared__ int rs[16], rt[16];
    __shared__ int base_s, base_t;
    const int g = blockIdx.x, t = threadIdx.x, lane = t & 31, wid = t >> 5;
    const int start = g * SCB;

    // ---- base = sum of all prior elements (parallel strided read) ----
    int ps = 0, pt = 0;
    for (int i = t; i < start && i < B; i += SCB) {
        ps += size[i]; pt += tsize[i];
    }
    #pragma unroll
    for (int o = 16; o > 0; o >>= 1) {
        ps += __shfl_xor_sync(0xffffffffu, ps, o);
        pt += __shfl_xor_sync(0xffffffffu, pt, o);
    }
    if (lane == 0) { rs[wid] = ps; rt[wid] = pt; }
    __syncthreads();
    if (t == 0) {
        int a = 0, c = 0;
        #pragma unroll
        for (int k = 0; k < 16; k++) { a += rs[k]; c += rt[k]; }
        base_s = a; base_t = c;
    }
    __syncthreads();

    // ---- block exclusive scan of this block's 512 elements ----
    const int i  = start + t;
    const int sv = (i < B) ? size[i]  : 0;
    const int tv = (i < B) ? tsize[i] : 0;
    int si = sv, ti = tv;
    #pragma unroll
    for (int o = 1; o < 32; o <<= 1) {
        const int a = __shfl_up_sync(0xffffffffu, si, o);
        const int c = __shfl_up_sync(0xffffffffu, ti, o);
        if (lane >= o) { si += a; ti += c; }
    }
    if (lane == 31) { rs[wid] = si; rt[wid] = ti; }
    __syncthreads();
    if (wid == 0 && lane < 16) {
        int a = rs[lane], c = rt[lane];
        #pragma unroll
        for (int o = 1; o < 16; o <<= 1) {
            const int x = __shfl_up_sync(0xffffu, a, o);
            const int y = __shfl_up_sync(0xffffu, c, o);
            if (lane >= o) { a += x; c += y; }
        }
        rs[lane] = a; rt[lane] = c;
    }
    __syncthreads();

    if (i < B) {
        const int es = (wid ? rs[wid - 1] : 0) + si - sv;
        const int et = (wid ? rt[wid - 1] : 0) + ti - tv;
        g_soff[i] = base_s + es;
        g_toff[i] = base_t + et;
    }
}

// ---------------------------------------------------------------------------
// helpers
// ---------------------------------------------------------------------------
__device__ __forceinline__ float4 f4add(float4 a, float4 b) {
    return make_float4(a.x + b.x, a.y + b.y, a.z + b.z, a.w + b.w);
}
__device__ __forceinline__ int pick_idx(int ia, int ib, int r) {
    const int v = __shfl_sync(0xffffffffu, ia, r & 31);
    const int w = __shfl_sync(0xffffffffu, ib, r & 31);
    return (r < 32) ? v : w;
}
template <int N>
__device__ __forceinline__ void red16(float (&v)[N]) {
    #pragma unroll
    for (int o = 8; o > 0; o >>= 1) {
        #pragma unroll
        for (int k = 0; k < N; k++)
            v[k] += __shfl_xor_sync(0xffffffffu, v[k], o);
    }
}

// ---------------------------------------------------------------------------
// Kernel 2 (round-4 champion body, capped to the champion's 32-reg budget):
// one warp per batch group; 16 lanes/row (quad q), halves h=0/1; item loop =
// 8 rows / 4 independent LDG.128 per lane-pair iteration; serialized
// 2-per-iter target loop.
// ---------------------------------------------------------------------------
__global__ void __launch_bounds__(TPB, 8)
simplex_kernel(const int*   __restrict__ user,
               const int*   __restrict__ item,
               const int*   __restrict__ tgt,
               const int*   __restrict__ size,
               const int*   __restrict__ tsize,
               const float* __restrict__ uw,
               const float* __restrict__ iw,
               float*       __restrict__ out,
               int B) {
    const int b = blockIdx.x * (TPB >> 5) + (threadIdx.x >> 5);
    if (b >= B) return;
    const int lane = threadIdx.x & 31;
    const int q    = lane & 15;
    const int h    = lane >> 4;

    const int soff = g_soff[b];
    const int toff = g_toff[b];
    const int sz   = size[b];
    const int tsz  = tsize[b];

    // ---- item segment sum: chunks of 64 indices, 8 rows / 4 loads per iter
    float4 acc0 = make_float4(0.f,0.f,0.f,0.f);
    float4 acc1 = make_float4(0.f,0.f,0.f,0.f);
    for (int cb = 0; cb < sz; cb += 64) {
        const int n  = min(sz - cb, 64);
        const int ia = (lane      < n) ? __ldg(&item[soff + cb + lane])      : 0;
        const int ib = (lane + 32 < n) ? __ldg(&item[soff + cb + 32 + lane]) : 0;

        int base = 0;
        for (; base + 8 <= n; base += 8) {
            const int i0 = pick_idx(ia, ib, base + 0 + h);
            const int i1 = pick_idx(ia, ib, base + 2 + h);
            const int i2 = pick_idx(ia, ib, base + 4 + h);
            const int i3 = pick_idx(ia, ib, base + 6 + h);
            const float4 v0 = __ldg((const float4*)&iw[(size_t)i0 * H + 4 * q]);
            const float4 v1 = __ldg((const float4*)&iw[(size_t)i1 * H + 4 * q]);
            const float4 v2 = __ldg((const float4*)&iw[(size_t)i2 * H + 4 * q]);
            const float4 v3 = __ldg((const float4*)&iw[(size_t)i3 * H + 4 * q]);
            acc0 = f4add(acc0, f4add(v0, v2));
            acc1 = f4add(acc1, f4add(v1, v3));
        }
        for (; base < n; base += 2) {
            const int r = base + h;
            if (r < n) {
                const int ii = pick_idx(ia, ib, r);
                acc0 = f4add(acc0, __ldg((const float4*)&iw[(size_t)ii * H + 4 * q]));
            }
        }
    }
    float4 acc = f4add(acc0, acc1);
    acc.x += __shfl_xor_sync(0xffffffffu, acc.x, 16);
    acc.y += __shfl_xor_sync(0xffffffffu, acc.y, 16);
    acc.z += __shfl_xor_sync(0xffffffffu, acc.z, 16);
    acc.w += __shfl_xor_sync(0xffffffffu, acc.w, 16);

    // ---- emb = 0.5*user + 0.5*mean ----
    const int ui   = max(soff + sz - 1, 0);
    const int urow = __ldg(&user[ui]);
    const float4 ue = __ldg((const float4*)&uw[(size_t)urow * H + 4 * q]);
    const float inv = 0.5f / ((float)sz + 1e-6f);
    float4 emb;
    emb.x = 0.5f * ue.x + acc.x * inv;
    emb.y = 0.5f * ue.y + acc.y * inv;
    emb.z = 0.5f * ue.z + acc.z * inv;
    emb.w = 0.5f * ue.w + acc.w * inv;

    // ---- center + L2 normalize (width-16, replicated in both halves) ----
    float v2r[2];
    v2r[0] = emb.x + emb.y + emb.z + emb.w;
    v2r[1] = emb.x*emb.x + emb.y*emb.y + emb.z*emb.z + emb.w*emb.w;
    red16<2>(v2r);
    const float mean = v2r[0] * (1.0f / H);
    const float ss   = fmaxf(v2r[1] - v2r[0] * mean, 0.0f);
    const float invn = 1.0f / fmaxf(sqrtf(ss), 1e-12f);
    float4 en;
    en.x = (emb.x - mean) * invn;
    en.y = (emb.y - mean) * invn;
    en.z = (emb.z - mean) * invn;
    en.w = (emb.w - mean) * invn;

    // ---- targets: two per iteration (one per half). sum(en)==0 so
    //      dot(center(te), en) == dot(te, en). ----
    for (int cb = 0; cb < tsz; cb += 32) {
        const int n  = min(tsz - cb, 32);
        const int ta = (lane < n) ? __ldg(&tgt[toff + cb + lane]) : 0;
        for (int base = 0; base < n; base += 2) {
            const int t = base + h;
            if (t < n) {
                const int row = __shfl_sync(0xffffffffu, ta, t);
                const float4 te = __ldg((const float4*)&iw[(size_t)row * H + 4 * q]);
                float v3[3];
                v3[0] = te.x + te.y + te.z + te.w;
                v3[1] = te.x*te.x + te.y*te.y + te.z*te.z + te.w*te.w;
                v3[2] = te.x*en.x + te.y*en.y + te.z*en.z + te.w*en.w;
                red16<3>(v3);
                if (q == 0) {
                    const float mt  = v3[0] * (1.0f / H);
                    const float sst = fmaxf(v3[1] - v3[0] * mt, 0.0f);
                    out[toff + cb + t] = v3[2] / fmaxf(sqrtf(sst), 1e-12f);
                }
            }
        }
    }
}

// ---------------------------------------------------------------------------
extern "C" void kernel_launch(void* const* d_in, const int* in_sizes, int n_in,
                              void* d_out, int out_size) {
    const int*   user        = (const int*)d_in[0];
    const int*   item        = (const int*)d_in[1];
    const int*   target_item = (const int*)d_in[2];
    const int*   size        = (const int*)d_in[3];
    const int*   target_size = (const int*)d_in[4];
    const float* user_weight = (const float*)d_in[5];
    const float* item_weight = (const float*)d_in[6];
    float*       out         = (float*)d_out;

    const int B     = in_sizes[3];
    const int nscan = (B + SCB - 1) / SCB;
    const int wpb   = TPB >> 5;
    const int grid  = (B + wpb - 1) / wpb;

    scan_par_kernel<<<nscan, SCB>>>(size, target_size, B);
    simplex_kernel<<<grid, TPB>>>(user, item, target_item, size, target_size,
                                  user_weight, item_weight, out, B);
}

// round 17
// speedup vs baseline: 1.4227x; 1.0753x over previous
#include <cuda_runtime.h>
#include <cuda_bf16.h>
#include <cstdint>

#define MAX_B  32768
#define H      64
#define TPB    256          // 8 warps = 8 batch groups per block
#define SCB    512          // elements per scan block

__device__ int g_soff[MAX_B];   // exclusive prefix of size
__device__ int g_toff[MAX_B];   // exclusive prefix of target_size

// ---------------------------------------------------------------------------
// Kernel 1: parallel redundant-prefix scan. Block g computes
// base = sum(size[0 : 512g]) by direct (parallel, L2-hot) re-read, then
// block-scans its own 512 elements and writes exact exclusive offsets.
// No inter-block communication; all blocks run concurrently.
// ---------------------------------------------------------------------------
__global__ void __launch_bounds__(SCB)
scan_par_kernel(const int* __restrict__ size, const int* __restrict__ tsize,
                int B) {
    __shared__ int rs[16], rt[16];
    __shared__ int base_s, base_t;
    const int g = blockIdx.x, t = threadIdx.x, lane = t & 31, wid = t >> 5;
    const int start = g * SCB;

    // ---- base = sum of all prior elements (parallel strided read) ----
    int ps = 0, pt = 0;
    for (int i = t; i < start && i < B; i += SCB) {
        ps += size[i]; pt += tsize[i];
    }
    #pragma unroll
    for (int o = 16; o > 0; o >>= 1) {
        ps += __shfl_xor_sync(0xffffffffu, ps, o);
        pt += __shfl_xor_sync(0xffffffffu, pt, o);
    }
    if (lane == 0) { rs[wid] = ps; rt[wid] = pt; }
    __syncthreads();
    if (t == 0) {
        int a = 0, c = 0;
        #pragma unroll
        for (int k = 0; k < 16; k++) { a += rs[k]; c += rt[k]; }
        base_s = a; base_t = c;
    }
    __syncthreads();

    // ---- block exclusive scan of this block's 512 elements ----
    const int i  = start + t;
    const int sv = (i < B) ? size[i]  : 0;
    const int tv = (i < B) ? tsize[i] : 0;
    int si = sv, ti = tv;
    #pragma unroll
    for (int o = 1; o < 32; o <<= 1) {
        const int a = __shfl_up_sync(0xffffffffu, si, o);
        const int c = __shfl_up_sync(0xffffffffu, ti, o);
        if (lane >= o) { si += a; ti += c; }
    }
    if (lane == 31) { rs[wid] = si; rt[wid] = ti; }
    __syncthreads();
    if (wid == 0 && lane < 16) {
        int a = rs[lane], c = rt[lane];
        #pragma unroll
        for (int o = 1; o < 16; o <<= 1) {
            const int x = __shfl_up_sync(0xffffu, a, o);
            const int y = __shfl_up_sync(0xffffu, c, o);
            if (lane >= o) { a += x; c += y; }
        }
        rs[lane] = a; rt[lane] = c;
    }
    __syncthreads();

    if (i < B) {
        const int es = (wid ? rs[wid - 1] : 0) + si - sv;
        const int et = (wid ? rt[wid - 1] : 0) + ti - tv;
        g_soff[i] = base_s + es;
        g_toff[i] = base_t + et;
    }
}

// ---------------------------------------------------------------------------
// helpers (champion set: NO pick_idx — inline ternary shuffles in the loop)
// ---------------------------------------------------------------------------
__device__ __forceinline__ float4 f4add(float4 a, float4 b) {
    return make_float4(a.x + b.x, a.y + b.y, a.z + b.z, a.w + b.w);
}
template <int N>
__device__ __forceinline__ void red16(float (&v)[N]) {
    #pragma unroll
    for (int o = 8; o > 0; o >>= 1) {
        #pragma unroll
        for (int k = 0; k < N; k++)
            v[k] += __shfl_xor_sync(0xffffffffu, v[k], o);
    }
}

// ---------------------------------------------------------------------------
// Kernel 2: ONE WARP per batch group. 16 lanes per row (lane q owns dims
// [4q,4q+4)), two rows in flight (one per half-warp), unrolled x4 for MLP.
// No block barriers in the hot path.  (Byte-identical to the 44.8us champion.)
// ---------------------------------------------------------------------------
__global__ void __launch_bounds__(TPB)
simplex_kernel(const int*   __restrict__ user,
               const int*   __restrict__ item,
               const int*   __restrict__ tgt,
               const int*   __restrict__ size,
               const int*   __restrict__ tsize,
               const float* __restrict__ uw,
               const float* __restrict__ iw,
               float*       __restrict__ out,
               int B) {
    const int b = blockIdx.x * (TPB >> 5) + (threadIdx.x >> 5);
    if (b >= B) return;
    const int lane = threadIdx.x & 31;
    const int q    = lane & 15;      // dim quad
    const int h    = lane >> 4;      // half-warp: which row of a pair

    const int soff = g_soff[b];
    const int toff = g_toff[b];
    const int sz   = size[b];
    const int tsz  = tsize[b];

    // ---- segment sum over item rows ----
    float4 acc = make_float4(0.f, 0.f, 0.f, 0.f);
    for (int cb = 0; cb < sz; cb += 64) {
        const int n = min(sz - cb, 64);
        // stash up to 64 indices in two registers (coalesced load)
        const int ia = (lane      < n) ? __ldg(&item[soff + cb + lane])      : 0;
        const int ib = (lane + 32 < n) ? __ldg(&item[soff + cb + 32 + lane]) : 0;

        int base = 0;
        for (; base + 8 <= n; base += 8) {
            const int r0 = base + 0 + h, r1 = base + 2 + h;
            const int r2 = base + 4 + h, r3 = base + 6 + h;
            const int i0 = (r0 < 32) ? __shfl_sync(0xffffffffu, ia, r0)
                                     : __shfl_sync(0xffffffffu, ib, r0 - 32);
            const int i1 = (r1 < 32) ? __shfl_sync(0xffffffffu, ia, r1)
                                     : __shfl_sync(0xffffffffu, ib, r1 - 32);
            const int i2 = (r2 < 32) ? __shfl_sync(0xffffffffu, ia, r2)
                                     : __shfl_sync(0xffffffffu, ib, r2 - 32);
            const int i3 = (r3 < 32) ? __shfl_sync(0xffffffffu, ia, r3)
                                     : __shfl_sync(0xffffffffu, ib, r3 - 32);
            // 4 independent gathers in flight per lane
            const float4 v0 = __ldg((const float4*)&iw[(size_t)i0 * H + 4 * q]);
            const float4 v1 = __ldg((const float4*)&iw[(size_t)i1 * H + 4 * q]);
            const float4 v2 = __ldg((const float4*)&iw[(size_t)i2 * H + 4 * q]);
            const float4 v3 = __ldg((const float4*)&iw[(size_t)i3 * H + 4 * q]);
            acc = f4add(acc, f4add(f4add(v0, v1), f4add(v2, v3)));
        }
        for (; base < n; base += 2) {
            const int r = base + h;
            if (r < n) {
                const int ii = (r < 32) ? __shfl_sync(0xffffffffu, ia, r)
                                        : __shfl_sync(0xffffffffu, ib, r - 32);
                acc = f4add(acc, __ldg((const float4*)&iw[(size_t)ii * H + 4 * q]));
            }
        }
    }
    // combine the two half-warp row streams (both halves hold the same quad q)
    acc.x += __shfl_xor_sync(0xffffffffu, acc.x, 16);
    acc.y += __shfl_xor_sync(0xffffffffu, acc.y, 16);
    acc.z += __shfl_xor_sync(0xffffffffu, acc.z, 16);
    acc.w += __shfl_xor_sync(0xffffffffu, acc.w, 16);

    // ---- emb = 0.5*user + 0.5*mean ----
    const int ui   = max(soff + sz - 1, 0);
    const int urow = __ldg(&user[ui]);
    const float4 ue = __ldg((const float4*)&uw[(size_t)urow * H + 4 * q]);
    const float inv = 0.5f / ((float)sz + 1e-6f);
    float4 emb;
    emb.x = 0.5f * ue.x + acc.x * inv;
    emb.y = 0.5f * ue.y + acc.y * inv;
    emb.z = 0.5f * ue.z + acc.z * inv;
    emb.w = 0.5f * ue.w + acc.w * inv;

    // ---- center + L2 normalize (width-16, replicated in both halves) ----
    float v2r[2];
    v2r[0] = emb.x + emb.y + emb.z + emb.w;
    v2r[1] = emb.x * emb.x + emb.y * emb.y + emb.z * emb.z + emb.w * emb.w;
    red16<2>(v2r);
    const float mean = v2r[0] * (1.0f / H);
    const float ss   = fmaxf(v2r[1] - v2r[0] * mean, 0.0f);
    const float invn = 1.0f / fmaxf(sqrtf(ss), 1e-12f);
    float4 en;
    en.x = (emb.x - mean) * invn;
    en.y = (emb.y - mean) * invn;
    en.z = (emb.z - mean) * invn;
    en.w = (emb.w - mean) * invn;

    // ---- targets: two per iteration (one per half). sum(en)==0 so
    //      dot(center(te), en) == dot(te, en). ----
    for (int cb = 0; cb < tsz; cb += 32) {
        const int n  = min(tsz - cb, 32);
        const int ta = (lane < n) ? __ldg(&tgt[toff + cb + lane]) : 0;
        for (int base = 0; base < n; base += 2) {
            const int t = base + h;
            if (t < n) {
                const int row = __shfl_sync(0xffffffffu, ta, t);
                const float4 te = __ldg((const float4*)&iw[(size_t)row * H + 4 * q]);
                float v3[3];
                v3[0] = te.x + te.y + te.z + te.w;
                v3[1] = te.x * te.x + te.y * te.y + te.z * te.z + te.w * te.w;
                v3[2] = te.x * en.x + te.y * en.y + te.z * en.z + te.w * en.w;
                red16<3>(v3);
                if (q == 0) {
                    const float mt  = v3[0] * (1.0f / H);
                    const float sst = fmaxf(v3[1] - v3[0] * mt, 0.0f);
                    out[toff + cb + t] = v3[2] / fmaxf(sqrtf(sst), 1e-12f);
                }
            }
        }
    }
}

// ---------------------------------------------------------------------------
extern "C" void kernel_launch(void* const* d_in, const int* in_sizes, int n_in,
                              void* d_out, int out_size) {
    const int*   user        = (const int*)d_in[0];
    const int*   item        = (const int*)d_in[1];
    const int*   target_item = (const int*)d_in[2];
    const int*   size        = (const int*)d_in[3];
    const int*   target_size = (const int*)d_in[4];
    const float* user_weight = (const float*)d_in[5];
    const float* item_weight = (const float*)d_in[6];
    float*       out         = (float*)d_out;

    const int B     = in_sizes[3];
    const int nscan = (B + SCB - 1) / SCB;
    const int wpb   = TPB >> 5;
    const int grid  = (B + wpb - 1) / wpb;

    scan_par_kernel<<<nscan, SCB>>>(size, target_size, B);
    simplex_kernel<<<grid, TPB>>>(user, item, target_item, size, target_size,
                                  user_weight, item_weight, out, B);
}